// round 6
// baseline (speedup 1.0000x reference)
#include <cuda_runtime.h>

#define G       37
#define NPATCH  (G * G)          // 1369
#define D       768
#define NCUE    5
#define STOK    (NCUE + NPATCH)  // 1374
#define BATCH   128
#define EPSN    1e-12f

#define TPB     128              // 4 warps
#define PTILE   256              // patch rows per block (2 per thread)
#define NT      6                // ceil(1369/256)
#define DC      16               // dims per pipeline stage
#define NS      (D / DC)         // 48 stages
#define F4ROW   (DC / 4)         // 4 float4 per row-stage
#define STAGE_F4 (PTILE * F4ROW) // 1024 float4 = 16KB per buffer

// packed argmax scratch: high 32 = orderable sim key, low 32 = ~idx (lowest idx
// wins ties). Zero-init at module load; gather_kernel resets after reading so
// every graph replay is deterministic.
__device__ unsigned long long g_best[BATCH * NCUE];

__device__ __forceinline__ unsigned f2key(float f) {
    unsigned u = __float_as_uint(f);
    return (u & 0x80000000u) ? ~u : (u | 0x80000000u);
}
__device__ __forceinline__ void fma2(unsigned long long& d, unsigned long long a,
                                     unsigned long long b) {
    asm volatile("fma.rn.f32x2 %0, %1, %2, %0;" : "+l"(d) : "l"(a), "l"(b));
}
__device__ __forceinline__ void lds_v2u64(unsigned long long& lo, unsigned long long& hi,
                                          unsigned addr) {
    asm volatile("ld.shared.v2.u64 {%0, %1}, [%2];" : "=l"(lo), "=l"(hi) : "r"(addr));
}
__device__ __forceinline__ void cp16(unsigned dst, const void* src) {
    asm volatile("cp.async.cg.shared.global [%0], [%1], 16;" :: "r"(dst), "l"(src)
                 : "memory");
}

// ---------------------------------------------------------------------------
// Kernel 1: per-(batch,cue) argmax over patch dot-products.
// P=2 rows/thread so each broadcast cue LDS.128 feeds 2 patch rows: warp LDS
// traffic drops from 2x(192x6) to 192x7 per 2 rows (1.7x), pushing the LDS
// crossbar (the R5 bottleneck, ~97us) to ~62us, below the DRAM floor.
// Warp-autonomous cp.async double buffer: warp w stages rows [64w,64w+64).
// Swizzle: float4 j of row R lives at R*64 + (j ^ ((R>>1)&3))*16 -> both the
// 2-row read pattern and the 8-row x 4-seg write pattern are phase-conflict-free.
// ---------------------------------------------------------------------------
__global__ __launch_bounds__(TPB, 4) void argmax_kernel(const float* __restrict__ tokens) {
    __shared__ float4 stage_buf[2][STAGE_F4];           // 32 KB
    __shared__ float  cue_sm[NCUE * D];                 // 15 KB
    __shared__ unsigned long long warp_best[TPB / 32][NCUE];

    const int b    = blockIdx.y;
    const int t    = threadIdx.x;
    const int lane = t & 31;
    const int warp = t >> 5;
    const float* base  = tokens + (size_t)b * STOK * D;
    const float* patch = base + NCUE * D;
    const unsigned sb0 = (unsigned)__cvta_generic_to_shared(&stage_buf[0][0]);
    const int p0 = blockIdx.x * PTILE;

    // Copy descriptors: instr q stages rows R = 64w + 8q + (lane>>2), seg lane&3.
    const int seg = lane & 3;
    const char* gsrc[8];
    unsigned    sdst[8];
#pragma unroll
    for (int q = 0; q < 8; q++) {
        const int R    = warp * 64 + q * 8 + (lane >> 2);
        const int pidx = min(p0 + R, NPATCH - 1);          // tail clamp (idempotent)
        gsrc[q] = (const char*)(patch + (size_t)pidx * D) + seg * 16;
        sdst[q] = sb0 + (unsigned)(R * 64 + ((seg ^ ((R >> 1) & 3)) * 16));
    }

#define ISSUE_STAGE(bufsel)                                                     \
    do {                                                                        \
        const unsigned _bo = (bufsel) ? (unsigned)(STAGE_F4 * 16) : 0u;         \
        _Pragma("unroll")                                                       \
        for (int _q = 0; _q < 8; _q++) {                                        \
            cp16(sdst[_q] + _bo, gsrc[_q]);                                     \
            gsrc[_q] += DC * 4;            /* next stage = +64B */              \
        }                                                                       \
        asm volatile("cp.async.commit_group;" ::: "memory");                    \
    } while (0)

    ISSUE_STAGE(0);
    ISSUE_STAGE(1);

    {   // cues -> smem (contiguous), one block barrier total
        const float4* cg = (const float4*)base;
        float4* cs = (float4*)cue_sm;
        for (int i = t; i < NCUE * D / 4; i += TPB) cs[i] = cg[i];
    }
    __syncthreads();

    // accumulators: 5 cues x 2 rows x 2 packed f32x2
    unsigned long long acc[NCUE][2][2];
#pragma unroll
    for (int c = 0; c < NCUE; c++)
#pragma unroll
        for (int r = 0; r < 2; r++) { acc[c][r][0] = 0ull; acc[c][r][1] = 0ull; }

    const int rA = warp * 64 + lane;        // row A
    const int rB = rA + 32;                 // row B (same swizzle: +32 keeps (R>>1)&3)
    const int sw = (rA >> 1) & 3;
    const unsigned rbA = sb0 + (unsigned)(rA * 64);
    const unsigned rbB = sb0 + (unsigned)(rB * 64);
    const unsigned cbase = (unsigned)__cvta_generic_to_shared(cue_sm);

    for (int s = 0; s < NS; s++) {
        if (s < NS - 1) asm volatile("cp.async.wait_group 1;" ::: "memory");
        else            asm volatile("cp.async.wait_group 0;" ::: "memory");
        __syncwarp();

        const unsigned bo = (s & 1) ? (unsigned)(STAGE_F4 * 16) : 0u;
        const unsigned cb = cbase + (unsigned)(s * DC * 4);
#pragma unroll
        for (int j = 0; j < F4ROW; j++) {
            const unsigned joff = (unsigned)(((j ^ sw) * 16));
            unsigned long long aLo, aHi, bLo, bHi;
            lds_v2u64(aLo, aHi, rbA + joff + bo);
            lds_v2u64(bLo, bHi, rbB + joff + bo);
#pragma unroll
            for (int c = 0; c < NCUE; c++) {
                unsigned long long qlo, qhi;
                lds_v2u64(qlo, qhi, cb + (unsigned)(c * D * 4 + j * 16));
                fma2(acc[c][0][0], aLo, qlo);
                fma2(acc[c][0][1], aHi, qhi);
                fma2(acc[c][1][0], bLo, qlo);
                fma2(acc[c][1][1], bHi, qhi);
            }
        }
        __syncwarp();
        if (s + 2 < NS) ISSUE_STAGE(s & 1);
    }
#undef ISSUE_STAGE

    // finalize: 2 sims/cue -> packed keys -> warp/block/global max
    const int pA = min(p0 + rA, NPATCH - 1);
    const int pB = min(p0 + rB, NPATCH - 1);
    const unsigned lbA = 0xFFFFFFFFu - (unsigned)pA;
    const unsigned lbB = 0xFFFFFFFFu - (unsigned)pB;
    unsigned long long key[NCUE];
#pragma unroll
    for (int c = 0; c < NCUE; c++) {
        float sA = (__uint_as_float((unsigned)(acc[c][0][0] & 0xFFFFFFFFull)) +
                    __uint_as_float((unsigned)(acc[c][0][0] >> 32))) +
                   (__uint_as_float((unsigned)(acc[c][0][1] & 0xFFFFFFFFull)) +
                    __uint_as_float((unsigned)(acc[c][0][1] >> 32)));
        float sB = (__uint_as_float((unsigned)(acc[c][1][0] & 0xFFFFFFFFull)) +
                    __uint_as_float((unsigned)(acc[c][1][0] >> 32))) +
                   (__uint_as_float((unsigned)(acc[c][1][1] & 0xFFFFFFFFull)) +
                    __uint_as_float((unsigned)(acc[c][1][1] >> 32)));
        unsigned long long kA = ((unsigned long long)f2key(sA) << 32) | lbA;
        unsigned long long kB = ((unsigned long long)f2key(sB) << 32) | lbB;
        key[c] = (kA > kB) ? kA : kB;
    }
#pragma unroll
    for (int c = 0; c < NCUE; c++)
#pragma unroll
        for (int o = 16; o; o >>= 1) {
            unsigned long long other = __shfl_xor_sync(0xffffffffu, key[c], o);
            key[c] = (other > key[c]) ? other : key[c];
        }
    if (lane == 0)
#pragma unroll
        for (int c = 0; c < NCUE; c++) warp_best[warp][c] = key[c];
    __syncthreads();
    if (t < NCUE) {
        unsigned long long m = warp_best[0][t];
#pragma unroll
        for (int w = 1; w < TPB / 32; w++)
            m = (warp_best[w][t] > m) ? warp_best[w][t] : m;
        atomicMax(&g_best[b * NCUE + t], m);
    }
}

// ---------------------------------------------------------------------------
// Kernel 2: one WARP per output token (128 blocks x 10 warps). Lane owns 24
// dims; 54 independent LDG.128 for the masked 3x3 ROI; shuffle-only reduce.
// No block barriers, no smem. Resets g_best for the next replay.
// ---------------------------------------------------------------------------
__global__ __launch_bounds__(320) void gather_kernel(const float* __restrict__ tokens,
                                                     float* __restrict__ out) {
    const int b    = blockIdx.x;
    const int tk   = threadIdx.x >> 5;     // 0..9
    const int lane = threadIdx.x & 31;
    const float* base = tokens + (size_t)b * STOK * D;

    float4 acc[6];

    if (tk < NCUE) {
        const float4* row = (const float4*)(base + (size_t)tk * D);
#pragma unroll
        for (int k = 0; k < 6; k++) acc[k] = row[lane + 32 * k];
    } else {
        const int c = tk - NCUE;
        const unsigned long long key = g_best[b * NCUE + c];
        const int idx = (int)(0xFFFFFFFFu - (unsigned)(key & 0xFFFFFFFFull));
        const int h = idx / G, w = idx % G;

        const float4* prow[9];
        float msk[9];
        float cnt = 0.0f;
#pragma unroll
        for (int dr = -1; dr <= 1; dr++)
#pragma unroll
            for (int dc = -1; dc <= 1; dc++) {
                const int k2 = (dr + 1) * 3 + (dc + 1);
                const int rr = h + dr, cc = w + dc;
                const bool ok = (rr >= 0) & (rr < G) & (cc >= 0) & (cc < G);
                const int rcl = min(max(rr, 0), G - 1);
                const int ccl = min(max(cc, 0), G - 1);
                prow[k2] = (const float4*)(base + (size_t)(NCUE + rcl * G + ccl) * D);
                msk[k2]  = ok ? 1.0f : 0.0f;
                cnt += msk[k2];
            }
        const float inv = 1.0f / cnt;
#pragma unroll
        for (int k = 0; k < 6; k++) acc[k] = make_float4(0.f, 0.f, 0.f, 0.f);
#pragma unroll
        for (int r = 0; r < 9; r++) {
            const float m = msk[r];
#pragma unroll
            for (int k = 0; k < 6; k++) {
                const float4 x = prow[r][lane + 32 * k];
                acc[k].x = fmaf(m, x.x, acc[k].x);
                acc[k].y = fmaf(m, x.y, acc[k].y);
                acc[k].z = fmaf(m, x.z, acc[k].z);
                acc[k].w = fmaf(m, x.w, acc[k].w);
            }
        }
#pragma unroll
        for (int k = 0; k < 6; k++) {
            acc[k].x *= inv; acc[k].y *= inv; acc[k].z *= inv; acc[k].w *= inv;
        }
        // reset scratch for next replay (after all lanes consumed the key)
        __syncwarp();
        if (lane == 0) g_best[b * NCUE + c] = 0ull;
    }

    float ss = 0.0f;
#pragma unroll
    for (int k = 0; k < 6; k++)
        ss += acc[k].x * acc[k].x + acc[k].y * acc[k].y +
              acc[k].z * acc[k].z + acc[k].w * acc[k].w;
#pragma unroll
    for (int o = 16; o > 0; o >>= 1) ss += __shfl_xor_sync(0xffffffffu, ss, o);

    const float scale = 1.0f / fmaxf(sqrtf(ss), EPSN);

    float4* orow = (float4*)(out + ((size_t)b * 10 + tk) * D);
#pragma unroll
    for (int k = 0; k < 6; k++) {
        float4 vv = acc[k];
        vv.x *= scale; vv.y *= scale; vv.z *= scale; vv.w *= scale;
        orow[lane + 32 * k] = vv;
    }
}

extern "C" void kernel_launch(void* const* d_in, const int* in_sizes, int n_in,
                              void* d_out, int out_size) {
    const float* tokens = (const float*)d_in[0];
    float* out = (float*)d_out;

    argmax_kernel<<<dim3(NT, BATCH), TPB>>>(tokens);
    gather_kernel<<<BATCH, 320>>>(tokens, out);
}